// round 13
// baseline (speedup 1.0000x reference)
#include <cuda_runtime.h>
#include <cuda_fp16.h>
#include <cstdint>
#include <math.h>

// Problem constants
#define B_   2
#define M_   2048
#define N_   2048
#define D_   2048
#define H_   16
#define DH_  128
#define DR_  64
#define DQK_ 192
#define SCALE_ 0.07216878364870323f  // 1/sqrt(192)

// ---------------- scratch (allocation-free: __device__ globals) ----------------
__device__ __half g_AqH [(size_t)B_ * M_ * D_];
__device__ __half g_AkvH[(size_t)B_ * N_ * D_];
__device__ __half g_WqcH[(size_t)H_ * DH_ * D_];
__device__ __half g_WkcH[(size_t)H_ * DH_ * D_];
__device__ __half g_WqrH[(size_t)H_ * DR_ * D_];
__device__ __half g_WkrH[(size_t)H_ * DR_ * D_];
__device__ __half g_WvH [(size_t)H_ * DH_ * D_];
__device__ __half g_WoH [(size_t)D_ * H_ * DH_];
__device__ __half g_QfH [(size_t)B_ * H_ * M_ * DQK_]; // perm-d, pre-scaled
__device__ __half g_KfH [(size_t)B_ * H_ * N_ * DQK_];
__device__ __half g_VpH [(size_t)B_ * H_ * N_ * DH_];
__device__ __half g_VtH [(size_t)B_ * H_ * DH_ * N_];  // (b,h,d,n), n perm
__device__ __half g_AoH [(size_t)B_ * M_ * (H_ * DH_)];
__device__ float g_cos[M_ * 32];
__device__ float g_sin[M_ * 32];

// ---------------- small PTX helpers ----------------
__device__ __forceinline__ void cp_async16h(__half* smem, const __half* gmem) {
    uint32_t s = (uint32_t)__cvta_generic_to_shared(smem);
    asm volatile("cp.async.cg.shared.global [%0], [%1], 16;\n" :: "r"(s), "l"(gmem) : "memory");
}
__device__ __forceinline__ void cp_commit() { asm volatile("cp.async.commit_group;\n" ::: "memory"); }
template <int N> __device__ __forceinline__ void cp_wait() {
    asm volatile("cp.async.wait_group %0;\n" :: "n"(N) : "memory");
}
__device__ __forceinline__ void mma_f16(float c[4],
        uint32_t a0, uint32_t a1, uint32_t a2, uint32_t a3,
        uint32_t b0, uint32_t b1) {
    asm volatile(
        "mma.sync.aligned.m16n8k16.row.col.f32.f16.f16.f32 "
        "{%0,%1,%2,%3},{%4,%5,%6,%7},{%8,%9},{%0,%1,%2,%3};\n"
        : "+f"(c[0]), "+f"(c[1]), "+f"(c[2]), "+f"(c[3])
        : "r"(a0), "r"(a1), "r"(a2), "r"(a3), "r"(b0), "r"(b1));
}
__device__ __forceinline__ uint32_t h2u(__half2 h) { return *(uint32_t*)&h; }
__device__ __forceinline__ int posk(int k) {
    return ((k >> 1) & 3) * 8 + ((k >> 3) & 3) * 2 + (k & 1);
}

// ---------------- fused fp32 -> fp16 convert (all 8 tensors, one kernel) ----------------
#define NBA 262144
#define NBW 131072
#define NBR 65536
#define NB_TOT (2 * NBA + 4 * NBW + 2 * NBR)   // 1179648

__global__ void conv_all(const float4* __restrict__ q,   const float4* __restrict__ kv,
                         const float4* __restrict__ wqc, const float4* __restrict__ wkc,
                         const float4* __restrict__ wv,  const float4* __restrict__ wo,
                         const float4* __restrict__ wqr, const float4* __restrict__ wkr) {
    int i = blockIdx.x * blockDim.x + threadIdx.x;
    if (i >= NB_TOT) return;
    const float4* s; uint4* d; int o = i;
    if (o < NBA)              { s = q;   d = (uint4*)g_AqH; }
    else if ((o -= NBA) < NBA){ s = kv;  d = (uint4*)g_AkvH; }
    else if ((o -= NBA) < NBW){ s = wqc; d = (uint4*)g_WqcH; }
    else if ((o -= NBW) < NBW){ s = wkc; d = (uint4*)g_WkcH; }
    else if ((o -= NBW) < NBW){ s = wv;  d = (uint4*)g_WvH; }
    else if ((o -= NBW) < NBW){ s = wo;  d = (uint4*)g_WoH; }
    else if ((o -= NBW) < NBR){ s = wqr; d = (uint4*)g_WqrH; }
    else { o -= NBR;            s = wkr; d = (uint4*)g_WkrH; }

    float v[32];
    const float4* sp = s + (size_t)o * 8;
#pragma unroll
    for (int j = 0; j < 8; ++j) {
        float4 f = sp[j];
        v[4*j] = f.x; v[4*j+1] = f.y; v[4*j+2] = f.z; v[4*j+3] = f.w;
    }
    uint4* dp = d + (size_t)o * 4;
#pragma unroll
    for (int t = 0; t < 4; ++t) {
        uint32_t h[4];
#pragma unroll
        for (int jj = 0; jj < 4; ++jj) {
            int k = 2 * t + 8 * jj;
            h[jj] = h2u(__floats2half2_rn(v[k], v[k + 1]));
        }
        dp[t] = make_uint4(h[0], h[1], h[2], h[3]);
    }
}

// ---------------- RoPE cache + apply (both Q and K in one launch) ----------------
__global__ void rope_cache_kernel() {
    int idx = blockIdx.x * blockDim.x + threadIdx.x;
    if (idx >= M_ * 32) return;
    int s = idx >> 5, i = idx & 31;
    double e = (double)(2 * i) / 64.0;
    float freq = (float)(1.0 / pow(1000000.0, e));
    float ang = (float)s * freq;
    double a = (double)ang;
    g_cos[idx] = (float)cos(a);
    g_sin[idx] = (float)sin(a);
}

#define ROPE_HALF (B_ * H_ * M_ * 32)
__global__ void rope_apply2() {
    int idx = blockIdx.x * blockDim.x + threadIdx.x;
    __half* buf;
    if (idx < ROPE_HALF) buf = g_QfH;
    else { idx -= ROPE_HALF; buf = g_KfH; }
    int i5 = idx & 31;
    int s = (idx >> 5) & (M_ - 1);
    int bh = idx >> 16;
    int blk = i5 >> 4, pp = i5 & 15;
    int qd = (pp >> 2) + ((pp & 3) << 2);
    int fi = blk * 16 + qd;
    size_t base = ((size_t)bh * M_ + s) * DQK_ + DH_ + blk * 32 + 2 * pp;
    float c = g_cos[(s << 5) + fi], sn = g_sin[(s << 5) + fi];
    __half2 xv = *(__half2*)(buf + base);
    float x0 = __low2float(xv), x1 = __high2float(xv);
    *(__half2*)(buf + base) = __floats2half2_rn(x0 * c - x1 * sn, x1 * c + x0 * sn);
}

// ---------------- V transpose: (b,h,n,d) -> (b,h,d,n) with n permuted ----------------
__global__ void transpose_v_kernel() {
    __shared__ __half ts[32][33];
    int bh = blockIdx.z;
    int d0 = blockIdx.x * 32, n0 = blockIdx.y * 32;
    const __half* src = g_VpH + (size_t)bh * N_ * DH_;
    __half* dst = g_VtH + (size_t)bh * DH_ * N_;
    int tx = threadIdx.x, ty = threadIdx.y;
#pragma unroll
    for (int i = 0; i < 32; i += 8)
        ts[ty + i][tx] = src[(size_t)(n0 + ty + i) * DH_ + d0 + tx];
    __syncthreads();
    int pn = posk(tx);
#pragma unroll
    for (int i = 0; i < 32; i += 8)
        dst[(size_t)(d0 + ty + i) * N_ + n0 + pn] = ts[tx][ty + i];
}

// ---------------- fp16 GEMM: tile 128x128x32, warp 64x64, RAW-split mma passes ----------------
#define G_ASZ 4096                              // halves per stage per operand
#define G_STG 4
#define GEMM_SMEM (G_STG * 2 * G_ASZ * 2)       // 65536 B

__global__ __launch_bounds__(128, 2)
void gemm_h(const __half* __restrict__ A, const __half* __restrict__ W,
            void* __restrict__ Cout, int mode, int dh, int ld, int off, float es) {
    extern __shared__ __half smh[];
    __half* smA = smh;
    __half* smB = smh + G_STG * G_ASZ;

    const int tid = threadIdx.x;
    const int m0 = blockIdx.y * 128;
    const int n0 = blockIdx.x * 128;
    const __half* Ab = A + (size_t)m0 * D_;
    const __half* Wb = W + (size_t)n0 * D_;

    auto load_stage = [&](int kt, int s) {
        const int k0 = kt * 32;
        __half* sa = smA + s * G_ASZ;
        __half* sb = smB + s * G_ASZ;
#pragma unroll
        for (int i = 0; i < 4; ++i) {
            int c = tid + i * 128;
            int row = c >> 2, t4 = c & 3;
            cp_async16h(sa + row * 32 + t4 * 8, Ab + (size_t)row * D_ + k0 + t4 * 8);
        }
#pragma unroll
        for (int i = 0; i < 4; ++i) {
            int c = tid + i * 128;
            int row = c >> 2, t4 = c & 3;
            cp_async16h(sb + row * 32 + t4 * 8, Wb + (size_t)row * D_ + k0 + t4 * 8);
        }
        cp_commit();
    };

    float acc[4][8][4] = {};
    const int warp = tid >> 5, lane = tid & 31;
    const int wm = warp >> 1, wn = warp & 1;   // 2x2 warps, warp tile 64x64
    const int g = lane >> 2, t = lane & 3;

    load_stage(0, 0); load_stage(1, 1); load_stage(2, 2);
    const int NKT = D_ / 32;   // 64
    for (int kt = 0; kt < NKT; ++kt) {
        if (kt + 3 < NKT)      { cp_wait<2>(); __syncthreads(); load_stage(kt + 3, (kt + 3) & 3); }
        else if (kt + 2 < NKT) { cp_wait<2>(); __syncthreads(); }
        else if (kt + 1 < NKT) { cp_wait<1>(); __syncthreads(); }
        else                   { cp_wait<0>(); __syncthreads(); }

        const uint4* sa = (const uint4*)(smA + (kt & 3) * G_ASZ);
        const uint4* sb = (const uint4*)(smB + (kt & 3) * G_ASZ);
        uint4 af[4][2];
#pragma unroll
        for (int im = 0; im < 4; ++im) {
            int r = wm * 64 + im * 16 + g;
            af[im][0] = sa[r * 4 + t];
            af[im][1] = sa[(r + 8) * 4 + t];
        }
        // RAW-split: per n-half, all step-0 mmas then all step-1 mmas (distance 16)
#pragma unroll
        for (int half = 0; half < 2; ++half) {
            uint4 bq[4];
#pragma unroll
            for (int q = 0; q < 4; ++q)
                bq[q] = sb[(wn * 64 + (half * 4 + q) * 8 + g) * 4 + t];
#pragma unroll
            for (int q = 0; q < 4; ++q)
#pragma unroll
                for (int im = 0; im < 4; ++im)
                    mma_f16(acc[im][half * 4 + q],
                            af[im][0].x, af[im][1].x, af[im][0].y, af[im][1].y,
                            bq[q].x, bq[q].y);
#pragma unroll
            for (int q = 0; q < 4; ++q)
#pragma unroll
                for (int im = 0; im < 4; ++im)
                    mma_f16(acc[im][half * 4 + q],
                            af[im][0].z, af[im][1].z, af[im][0].w, af[im][1].w,
                            bq[q].z, bq[q].w);
        }
    }

#pragma unroll
    for (int im = 0; im < 4; ++im) {
        int r0g = m0 + wm * 64 + im * 16 + g;
#pragma unroll
        for (int in = 0; in < 8; ++in) {
            int c0 = n0 + wn * 64 + in * 8 + 2 * t;
            if (mode == 2) {
                float* C = (float*)Cout;
                *(float2*)&C[(size_t)r0g * 2048 + c0] =
                    make_float2(acc[im][in][0], acc[im][in][1]);
                *(float2*)&C[(size_t)(r0g + 8) * 2048 + c0] =
                    make_float2(acc[im][in][2], acc[im][in][3]);
            } else {
                __half* C = (__half*)Cout;
                int b = r0g >> 11, m = r0g & (M_ - 1);
                int h = c0 / dh, d = c0 - h * dh;
                int dcol = (mode == 0) ? ((d & ~31) + posk(d & 31)) : d;
                size_t base = (((size_t)(b * H_ + h) * M_) + m) * ld + off + dcol;
                *(__half2*)&C[base] = __floats2half2_rn(acc[im][in][0] * es, acc[im][in][1] * es);
                *(__half2*)&C[base + (size_t)8 * ld] =
                    __floats2half2_rn(acc[im][in][2] * es, acc[im][in][3] * es);
            }
        }
    }
}

// ---------------- fused flash attention fp16 (Br=64, Bc=64, 4 warps, 2 CTA/SM) ----------------
#define FL_KOFF 12288
#define FL_VOFF 36864
#define FLASH_SMEM (53248 * 2)

__global__ __launch_bounds__(128, 2)
void flash_kernel() {
    extern __shared__ __half smh[];
    __half* Qs = smh;
    __half* Ks = smh + FL_KOFF;
    __half* Vs = smh + FL_VOFF;

    const int tid = threadIdx.x;
    const int m0 = blockIdx.x * 64;
    const int bh = blockIdx.y;
    const int b = bh >> 4, h = bh & 15;

    const __half* Qg = g_QfH + ((size_t)bh * M_ + m0) * DQK_;
    const __half* Kg = g_KfH + (size_t)bh * N_ * DQK_;
    const __half* Vg = g_VtH + (size_t)bh * DH_ * N_;

#pragma unroll
    for (int i = 0; i < 12; ++i) {
        int c = tid + i * 128;
        int row = c / 24, cc = c % 24;
        int phys = cc ^ ((row & 1) << 2);
        cp_async16h(Qs + row * 192 + phys * 8, Qg + (size_t)row * 192 + cc * 8);
    }
    cp_commit();

    auto load_K = [&](int j, int buf) {
        const __half* src = Kg + (size_t)j * 64 * DQK_;
        __half* dst = Ks + buf * 12288;
#pragma unroll
        for (int i = 0; i < 12; ++i) {
            int c = tid + i * 128;
            int row = c / 24, cc = c % 24;
            int phys = cc ^ ((row & 1) << 2);
            cp_async16h(dst + row * 192 + phys * 8, src + (size_t)row * 192 + cc * 8);
        }
        cp_commit();
    };
    auto load_V = [&](int j, int buf) {
        __half* dst = Vs + buf * 8192;
#pragma unroll
        for (int i = 0; i < 8; ++i) {
            int c = tid + i * 128;
            int row = c >> 3, cc = c & 7;
            int phys = cc ^ ((row & 1) << 2);
            cp_async16h(dst + row * 64 + phys * 8, Vg + (size_t)row * N_ + j * 64 + cc * 8);
        }
        cp_commit();
    };

    load_K(0, 0);
    load_V(0, 0);

    const int warp = tid >> 5, lane = tid & 31;
    const int g = lane >> 2, t = lane & 3;
    const int r0 = warp * 16 + g;
    const int swz = (g & 1) << 2;
    const int qr0 = r0 * 24, qr1 = (r0 + 8) * 24;

    float o[16][4] = {};
    float m0r = -1e30f, m1r = -1e30f, l0 = 0.f, l1 = 0.f;

    for (int j = 0; j < N_ / 64; ++j) {
        cp_wait<0>();
        __syncthreads();
        if (j + 1 < N_ / 64) { load_K(j + 1, (j + 1) & 1); load_V(j + 1, (j + 1) & 1); }

        const uint4* Ks4 = (const uint4*)(Ks + (j & 1) * 12288);
        const uint4* Vs4 = (const uint4*)(Vs + (j & 1) * 8192);
        const uint4* Qs4 = (const uint4*)Qs;

        // ---- S = Q K^T : RAW-split passes (distance 8) ----
        float s[8][4] = {};
#pragma unroll
        for (int blk = 0; blk < 6; ++blk) {
            int c = (blk * 4 + t) ^ swz;
            uint4 q0 = Qs4[qr0 + c];
            uint4 q1 = Qs4[qr1 + c];
            uint4 kq[8];
#pragma unroll
            for (int nf = 0; nf < 8; ++nf)
                kq[nf] = Ks4[(nf * 8 + g) * 24 + c];
#pragma unroll
            for (int nf = 0; nf < 8; ++nf)
                mma_f16(s[nf], q0.x, q1.x, q0.y, q1.y, kq[nf].x, kq[nf].y);
#pragma unroll
            for (int nf = 0; nf < 8; ++nf)
                mma_f16(s[nf], q0.z, q1.z, q0.w, q1.w, kq[nf].z, kq[nf].w);
        }

        // ---- warp-local online softmax (Q pre-scaled) ----
        float mx0 = -1e30f, mx1 = -1e30f;
#pragma unroll
        for (int nf = 0; nf < 8; ++nf) {
            mx0 = fmaxf(mx0, fmaxf(s[nf][0], s[nf][1]));
            mx1 = fmaxf(mx1, fmaxf(s[nf][2], s[nf][3]));
        }
        mx0 = fmaxf(mx0, __shfl_xor_sync(0xffffffffu, mx0, 1));
        mx0 = fmaxf(mx0, __shfl_xor_sync(0xffffffffu, mx0, 2));
        mx1 = fmaxf(mx1, __shfl_xor_sync(0xffffffffu, mx1, 1));
        mx1 = fmaxf(mx1, __shfl_xor_sync(0xffffffffu, mx1, 2));
        float nm0 = fmaxf(m0r, mx0), nm1 = fmaxf(m1r, mx1);
        float sc0 = __expf(m0r - nm0), sc1 = __expf(m1r - nm1);
        m0r = nm0; m1r = nm1;

        float sum0 = 0.f, sum1 = 0.f;
        uint32_t plo[8], phi[8];
#pragma unroll
        for (int nf = 0; nf < 8; ++nf) {
            float p0 = __expf(s[nf][0] - m0r), p1 = __expf(s[nf][1] - m0r);
            float p2 = __expf(s[nf][2] - m1r), p3 = __expf(s[nf][3] - m1r);
            sum0 += p0 + p1; sum1 += p2 + p3;
            plo[nf] = h2u(__floats2half2_rn(p0, p1));
            phi[nf] = h2u(__floats2half2_rn(p2, p3));
        }
        sum0 += __shfl_xor_sync(0xffffffffu, sum0, 1);
        sum0 += __shfl_xor_sync(0xffffffffu, sum0, 2);
        sum1 += __shfl_xor_sync(0xffffffffu, sum1, 1);
        sum1 += __shfl_xor_sync(0xffffffffu, sum1, 2);
        l0 = l0 * sc0 + sum0;
        l1 = l1 * sc1 + sum1;
#pragma unroll
        for (int nf = 0; nf < 16; ++nf) {
            o[nf][0] *= sc0; o[nf][1] *= sc0; o[nf][2] *= sc1; o[nf][3] *= sc1;
        }

        // ---- O += P @ V : RAW-split passes (distance 8) ----
#pragma unroll
        for (int blk = 0; blk < 2; ++blk) {
            int c = (blk * 4 + t) ^ swz;
            uint32_t a00 = plo[4*blk],     a01 = phi[4*blk];
            uint32_t a02 = plo[4*blk + 1], a03 = phi[4*blk + 1];
            uint32_t a10 = plo[4*blk + 2], a11 = phi[4*blk + 2];
            uint32_t a12 = plo[4*blk + 3], a13 = phi[4*blk + 3];
#pragma unroll
            for (int hh = 0; hh < 2; ++hh) {
                uint4 vq[8];
#pragma unroll
                for (int q = 0; q < 8; ++q)
                    vq[q] = Vs4[((hh * 8 + q) * 8 + g) * 8 + c];
#pragma unroll
                for (int q = 0; q < 8; ++q)
                    mma_f16(o[hh * 8 + q], a00, a01, a02, a03, vq[q].x, vq[q].y);
#pragma unroll
                for (int q = 0; q < 8; ++q)
                    mma_f16(o[hh * 8 + q], a10, a11, a12, a13, vq[q].z, vq[q].w);
            }
        }
    }

    float inv0 = 1.f / l0;
    float inv1 = 1.f / l1;
#pragma unroll
    for (int nf = 0; nf < 16; ++nf) {
        int cpos = h * 128 + (nf >> 2) * 32 + 8 * t + 2 * (nf & 3);
        size_t base0 = ((size_t)(b * M_) + m0 + r0) * 2048 + cpos;
        *(__half2*)&g_AoH[base0] = __floats2half2_rn(o[nf][0] * inv0, o[nf][1] * inv0);
        *(__half2*)&g_AoH[base0 + (size_t)8 * 2048] =
            __floats2half2_rn(o[nf][2] * inv1, o[nf][3] * inv1);
    }
}

// ---------------- launch ----------------
extern "C" void kernel_launch(void* const* d_in, const int* in_sizes, int n_in,
                              void* d_out, int out_size) {
    const float* query = (const float*)d_in[0];
    const float* keyv  = (const float*)d_in[1];
    const float* W_QC  = (const float*)d_in[2];
    const float* W_KC  = (const float*)d_in[3];
    const float* W_QR  = (const float*)d_in[4];
    const float* W_KR  = (const float*)d_in[5];
    const float* W_V   = (const float*)d_in[6];
    const float* W_O   = (const float*)d_in[7];
    float* out = (float*)d_out;

    static __half *pAq = nullptr, *pAkv, *pWqc, *pWkc, *pWqr, *pWkr, *pWv, *pWo;
    static __half *pQf, *pKf, *pVp, *pAo;
    if (!pAq) {
        cudaFuncSetAttribute(gemm_h, cudaFuncAttributeMaxDynamicSharedMemorySize, GEMM_SMEM);
        cudaFuncSetAttribute(flash_kernel, cudaFuncAttributeMaxDynamicSharedMemorySize, FLASH_SMEM);
        cudaGetSymbolAddress((void**)&pAq,  g_AqH);
        cudaGetSymbolAddress((void**)&pAkv, g_AkvH);
        cudaGetSymbolAddress((void**)&pWqc, g_WqcH);
        cudaGetSymbolAddress((void**)&pWkc, g_WkcH);
        cudaGetSymbolAddress((void**)&pWqr, g_WqrH);
        cudaGetSymbolAddress((void**)&pWkr, g_WkrH);
        cudaGetSymbolAddress((void**)&pWv,  g_WvH);
        cudaGetSymbolAddress((void**)&pWo,  g_WoH);
        cudaGetSymbolAddress((void**)&pQf,  g_QfH);
        cudaGetSymbolAddress((void**)&pKf,  g_KfH);
        cudaGetSymbolAddress((void**)&pVp,  g_VpH);
        cudaGetSymbolAddress((void**)&pAo,  g_AoH);
    }

    rope_cache_kernel<<<256, 256>>>();

    conv_all<<<(NB_TOT + 255) / 256, 256>>>(
        (const float4*)query, (const float4*)keyv,
        (const float4*)W_QC, (const float4*)W_KC,
        (const float4*)W_V,  (const float4*)W_O,
        (const float4*)W_QR, (const float4*)W_KR);

    dim3 thr(128);
    gemm_h<<<dim3(16, 32), thr, GEMM_SMEM>>>(pAq,  pWqc, pQf, 0, 128, 192, 0,   SCALE_);
    gemm_h<<<dim3(8, 32),  thr, GEMM_SMEM>>>(pAq,  pWqr, pQf, 0, 64, 192, 128,  SCALE_);
    gemm_h<<<dim3(16, 32), thr, GEMM_SMEM>>>(pAkv, pWkc, pKf, 0, 128, 192, 0,   1.0f);
    gemm_h<<<dim3(8, 32),  thr, GEMM_SMEM>>>(pAkv, pWkr, pKf, 0, 64, 192, 128,  1.0f);
    gemm_h<<<dim3(16, 32), thr, GEMM_SMEM>>>(pAkv, pWv,  pVp, 1, 128, 128, 0,   1.0f);
    transpose_v_kernel<<<dim3(4, 64, 32), dim3(32, 8)>>>();
    rope_apply2<<<2 * ROPE_HALF / 256, 256>>>();
    flash_kernel<<<dim3(32, 32), thr, FLASH_SMEM>>>();
    gemm_h<<<dim3(16, 32), thr, GEMM_SMEM>>>(pAo, pWo, out, 2, 1, 2048, 0, 1.0f);
}

// round 15
// speedup vs baseline: 1.6724x; 1.6724x over previous
#include <cuda_runtime.h>
#include <cuda_fp16.h>
#include <cstdint>
#include <math.h>

// Problem constants
#define B_   2
#define M_   2048
#define N_   2048
#define D_   2048
#define H_   16
#define DH_  128
#define DR_  64
#define DQK_ 192
#define SCALE_ 0.07216878364870323f  // 1/sqrt(192)

// ---------------- scratch (allocation-free: __device__ globals) ----------------
__device__ __half g_AqH [(size_t)B_ * M_ * D_];
__device__ __half g_AkvH[(size_t)B_ * N_ * D_];
__device__ __half g_WqcH[(size_t)H_ * DH_ * D_];
__device__ __half g_WkcH[(size_t)H_ * DH_ * D_];
__device__ __half g_WqrH[(size_t)H_ * DR_ * D_];
__device__ __half g_WkrH[(size_t)H_ * DR_ * D_];
__device__ __half g_WvH [(size_t)H_ * DH_ * D_];
__device__ __half g_WoH [(size_t)D_ * H_ * DH_];
__device__ __half g_QfH [(size_t)B_ * H_ * M_ * DQK_]; // perm-d, pre-scaled, roped
__device__ __half g_KfH [(size_t)B_ * H_ * N_ * DQK_];
__device__ __half g_VpH [(size_t)B_ * H_ * N_ * DH_];  // V proj, UNpermuted d
__device__ __half g_VtH [(size_t)B_ * H_ * DH_ * N_];  // (b,h,d,n), n perm
__device__ __half g_AoH [(size_t)B_ * M_ * (H_ * DH_)];
__device__ float g_cos[M_ * 32];
__device__ float g_sin[M_ * 32];

// ---------------- small PTX helpers ----------------
__device__ __forceinline__ void cp_async16h(__half* smem, const __half* gmem) {
    uint32_t s = (uint32_t)__cvta_generic_to_shared(smem);
    asm volatile("cp.async.cg.shared.global [%0], [%1], 16;\n" :: "r"(s), "l"(gmem) : "memory");
}
__device__ __forceinline__ void cp_commit() { asm volatile("cp.async.commit_group;\n" ::: "memory"); }
template <int N> __device__ __forceinline__ void cp_wait() {
    asm volatile("cp.async.wait_group %0;\n" :: "n"(N) : "memory");
}
__device__ __forceinline__ void mma_f16(float c[4],
        uint32_t a0, uint32_t a1, uint32_t a2, uint32_t a3,
        uint32_t b0, uint32_t b1) {
    asm volatile(
        "mma.sync.aligned.m16n8k16.row.col.f32.f16.f16.f32 "
        "{%0,%1,%2,%3},{%4,%5,%6,%7},{%8,%9},{%0,%1,%2,%3};\n"
        : "+f"(c[0]), "+f"(c[1]), "+f"(c[2]), "+f"(c[3])
        : "r"(a0), "r"(a1), "r"(a2), "r"(a3), "r"(b0), "r"(b1));
}
__device__ __forceinline__ uint32_t h2u(__half2 h) { return *(uint32_t*)&h; }
__device__ __forceinline__ int posk(int k) {
    return ((k >> 1) & 3) * 8 + ((k >> 3) & 3) * 2 + (k & 1);
}

// ---------------- fused fp32 -> fp16 convert (all 8 tensors, one kernel) ----------------
#define NBA 262144
#define NBW 131072
#define NBR 65536
#define NB_TOT (2 * NBA + 4 * NBW + 2 * NBR)   // 1179648

__global__ void conv_all(const float4* __restrict__ q,   const float4* __restrict__ kv,
                         const float4* __restrict__ wqc, const float4* __restrict__ wkc,
                         const float4* __restrict__ wv,  const float4* __restrict__ wo,
                         const float4* __restrict__ wqr, const float4* __restrict__ wkr) {
    int i = blockIdx.x * blockDim.x + threadIdx.x;
    if (i >= NB_TOT) return;
    const float4* s; uint4* d; int o = i;
    if (o < NBA)              { s = q;   d = (uint4*)g_AqH; }
    else if ((o -= NBA) < NBA){ s = kv;  d = (uint4*)g_AkvH; }
    else if ((o -= NBA) < NBW){ s = wqc; d = (uint4*)g_WqcH; }
    else if ((o -= NBW) < NBW){ s = wkc; d = (uint4*)g_WkcH; }
    else if ((o -= NBW) < NBW){ s = wv;  d = (uint4*)g_WvH; }
    else if ((o -= NBW) < NBW){ s = wo;  d = (uint4*)g_WoH; }
    else if ((o -= NBW) < NBR){ s = wqr; d = (uint4*)g_WqrH; }
    else { o -= NBR;            s = wkr; d = (uint4*)g_WkrH; }

    float v[32];
    const float4* sp = s + (size_t)o * 8;
#pragma unroll
    for (int j = 0; j < 8; ++j) {
        float4 f = sp[j];
        v[4*j] = f.x; v[4*j+1] = f.y; v[4*j+2] = f.z; v[4*j+3] = f.w;
    }
    uint4* dp = d + (size_t)o * 4;
#pragma unroll
    for (int t = 0; t < 4; ++t) {
        uint32_t h[4];
#pragma unroll
        for (int jj = 0; jj < 4; ++jj) {
            int k = 2 * t + 8 * jj;
            h[jj] = h2u(__floats2half2_rn(v[k], v[k + 1]));
        }
        dp[t] = make_uint4(h[0], h[1], h[2], h[3]);
    }
}

// ---------------- RoPE cache ----------------
__global__ void rope_cache_kernel() {
    int idx = blockIdx.x * blockDim.x + threadIdx.x;
    if (idx >= M_ * 32) return;
    int s = idx >> 5, i = idx & 31;
    double e = (double)(2 * i) / 64.0;
    float freq = (float)(1.0 / pow(1000000.0, e));
    float ang = (float)s * freq;
    double a = (double)ang;
    g_cos[idx] = (float)cos(a);
    g_sin[idx] = (float)sin(a);
}

// ---------------- V transpose: (b,h,n,d) -> (b,h,d,n) with n permuted ----------------
__global__ void transpose_v_kernel() {
    __shared__ __half ts[32][33];
    int bh = blockIdx.z;
    int d0 = blockIdx.x * 32, n0 = blockIdx.y * 32;
    const __half* src = g_VpH + (size_t)bh * N_ * DH_;
    __half* dst = g_VtH + (size_t)bh * DH_ * N_;
    int tx = threadIdx.x, ty = threadIdx.y;
#pragma unroll
    for (int i = 0; i < 32; i += 8)
        ts[ty + i][tx] = src[(size_t)(n0 + ty + i) * DH_ + d0 + tx];
    __syncthreads();
    int pn = posk(tx);
#pragma unroll
    for (int i = 0; i < 32; i += 8)
        dst[(size_t)(d0 + ty + i) * N_ + n0 + pn] = ts[tx][ty + i];
}

// ---------------- GEMM cores (R12 inner loop) ----------------
#define G_ASZ 4096                              // halves per stage per operand
#define G_STG 4
#define GEMM_SMEM (G_STG * 2 * G_ASZ * 2)       // 65536 B

// all-projection fused GEMM: jobs on blockIdx.x
//  [0,16): Qc  [16,24): Qr(+rope)  [24,40): Kc  [40,48): Kr(+rope)  [48,64): V
__global__ __launch_bounds__(128, 2)
void proj_all() {
    extern __shared__ __half smh[];
    __half* smA = smh;
    __half* smB = smh + G_STG * G_ASZ;

    const int tid = threadIdx.x;
    const int jx = blockIdx.x;
    const __half *A, *W;
    __half* C;
    int nx, dh, ld, off, rope, perm;
    float es;
    if (jx < 16)      { A = g_AqH;  W = g_WqcH; C = g_QfH; nx = jx;      dh = 128; ld = 192; off = 0;   es = SCALE_; rope = 0; perm = 1; }
    else if (jx < 24) { A = g_AqH;  W = g_WqrH; C = g_QfH; nx = jx - 16; dh = 64;  ld = 192; off = 128; es = SCALE_; rope = 1; perm = 1; }
    else if (jx < 40) { A = g_AkvH; W = g_WkcH; C = g_KfH; nx = jx - 24; dh = 128; ld = 192; off = 0;   es = 1.0f;   rope = 0; perm = 1; }
    else if (jx < 48) { A = g_AkvH; W = g_WkrH; C = g_KfH; nx = jx - 40; dh = 64;  ld = 192; off = 128; es = 1.0f;   rope = 1; perm = 1; }
    else              { A = g_AkvH; W = g_WvH;  C = g_VpH; nx = jx - 48; dh = 128; ld = 128; off = 0;   es = 1.0f;   rope = 0; perm = 0; }

    const int m0 = blockIdx.y * 128;
    const int n0 = nx * 128;
    const __half* Ab = A + (size_t)m0 * D_;
    const __half* Wb = W + (size_t)n0 * D_;

    auto load_stage = [&](int kt, int s) {
        const int k0 = kt * 32;
        __half* sa = smA + s * G_ASZ;
        __half* sb = smB + s * G_ASZ;
#pragma unroll
        for (int i = 0; i < 4; ++i) {
            int c = tid + i * 128;
            int row = c >> 2, t4 = c & 3;
            cp_async16h(sa + row * 32 + t4 * 8, Ab + (size_t)row * D_ + k0 + t4 * 8);
        }
#pragma unroll
        for (int i = 0; i < 4; ++i) {
            int c = tid + i * 128;
            int row = c >> 2, t4 = c & 3;
            cp_async16h(sb + row * 32 + t4 * 8, Wb + (size_t)row * D_ + k0 + t4 * 8);
        }
        cp_commit();
    };

    float acc[4][8][4] = {};
    const int warp = tid >> 5, lane = tid & 31;
    const int wm = warp >> 1, wn = warp & 1;   // 2x2 warps, warp tile 64x64
    const int g = lane >> 2, t = lane & 3;

    load_stage(0, 0); load_stage(1, 1); load_stage(2, 2);
    const int NKT = D_ / 32;   // 64
    for (int kt = 0; kt < NKT; ++kt) {
        if (kt + 3 < NKT)      { cp_wait<2>(); __syncthreads(); load_stage(kt + 3, (kt + 3) & 3); }
        else if (kt + 2 < NKT) { cp_wait<2>(); __syncthreads(); }
        else if (kt + 1 < NKT) { cp_wait<1>(); __syncthreads(); }
        else                   { cp_wait<0>(); __syncthreads(); }

        const uint4* sa = (const uint4*)(smA + (kt & 3) * G_ASZ);
        const uint4* sb = (const uint4*)(smB + (kt & 3) * G_ASZ);
        uint4 af[4][2];
#pragma unroll
        for (int im = 0; im < 4; ++im) {
            int r = wm * 64 + im * 16 + g;
            af[im][0] = sa[r * 4 + t];
            af[im][1] = sa[(r + 8) * 4 + t];
        }
#pragma unroll
        for (int in = 0; in < 8; ++in) {
            uint4 bq = sb[(wn * 64 + in * 8 + g) * 4 + t];
#pragma unroll
            for (int im = 0; im < 4; ++im) {
                mma_f16(acc[im][in], af[im][0].x, af[im][1].x, af[im][0].y, af[im][1].y, bq.x, bq.y);
                mma_f16(acc[im][in], af[im][0].z, af[im][1].z, af[im][0].w, af[im][1].w, bq.z, bq.w);
            }
        }
    }

#pragma unroll
    for (int im = 0; im < 4; ++im) {
        int r0g = m0 + wm * 64 + im * 16 + g;
        int b = r0g >> 11, m = r0g & (M_ - 1);
#pragma unroll
        for (int in = 0; in < 8; ++in) {
            int c0 = n0 + wn * 64 + in * 8 + 2 * t;
            int h = c0 / dh, d = c0 - h * dh;
            float v0 = acc[im][in][0] * es, v1 = acc[im][in][1] * es;
            float v2 = acc[im][in][2] * es, v3 = acc[im][in][3] * es;
            if (rope) {
                int i2 = d >> 1;
                float c_a = g_cos[(m << 5) + i2],        s_a = g_sin[(m << 5) + i2];
                float c_b = g_cos[((m + 8) << 5) + i2],  s_b = g_sin[((m + 8) << 5) + i2];
                float t0 = v0 * c_a - v1 * s_a, t1 = v1 * c_a + v0 * s_a;
                float t2 = v2 * c_b - v3 * s_b, t3 = v3 * c_b + v2 * s_b;
                v0 = t0; v1 = t1; v2 = t2; v3 = t3;
            }
            int dcol = perm ? ((d & ~31) + posk(d & 31)) : d;
            size_t base = (((size_t)(b * H_ + h) * M_) + m) * ld + off + dcol;
            *(__half2*)&C[base] = __floats2half2_rn(v0, v1);
            *(__half2*)&C[base + (size_t)8 * ld] = __floats2half2_rn(v2, v3);
        }
    }
}

// final GEMM: out = Ao @ Wo^T (fp32 out)
__global__ __launch_bounds__(128, 2)
void gemm_out(const __half* __restrict__ A, const __half* __restrict__ W,
              float* __restrict__ C) {
    extern __shared__ __half smh[];
    __half* smA = smh;
    __half* smB = smh + G_STG * G_ASZ;

    const int tid = threadIdx.x;
    const int m0 = blockIdx.y * 128;
    const int n0 = blockIdx.x * 128;
    const __half* Ab = A + (size_t)m0 * D_;
    const __half* Wb = W + (size_t)n0 * D_;

    auto load_stage = [&](int kt, int s) {
        const int k0 = kt * 32;
        __half* sa = smA + s * G_ASZ;
        __half* sb = smB + s * G_ASZ;
#pragma unroll
        for (int i = 0; i < 4; ++i) {
            int c = tid + i * 128;
            int row = c >> 2, t4 = c & 3;
            cp_async16h(sa + row * 32 + t4 * 8, Ab + (size_t)row * D_ + k0 + t4 * 8);
        }
#pragma unroll
        for (int i = 0; i < 4; ++i) {
            int c = tid + i * 128;
            int row = c >> 2, t4 = c & 3;
            cp_async16h(sb + row * 32 + t4 * 8, Wb + (size_t)row * D_ + k0 + t4 * 8);
        }
        cp_commit();
    };

    float acc[4][8][4] = {};
    const int warp = tid >> 5, lane = tid & 31;
    const int wm = warp >> 1, wn = warp & 1;
    const int g = lane >> 2, t = lane & 3;

    load_stage(0, 0); load_stage(1, 1); load_stage(2, 2);
    const int NKT = D_ / 32;
    for (int kt = 0; kt < NKT; ++kt) {
        if (kt + 3 < NKT)      { cp_wait<2>(); __syncthreads(); load_stage(kt + 3, (kt + 3) & 3); }
        else if (kt + 2 < NKT) { cp_wait<2>(); __syncthreads(); }
        else if (kt + 1 < NKT) { cp_wait<1>(); __syncthreads(); }
        else                   { cp_wait<0>(); __syncthreads(); }

        const uint4* sa = (const uint4*)(smA + (kt & 3) * G_ASZ);
        const uint4* sb = (const uint4*)(smB + (kt & 3) * G_ASZ);
        uint4 af[4][2];
#pragma unroll
        for (int im = 0; im < 4; ++im) {
            int r = wm * 64 + im * 16 + g;
            af[im][0] = sa[r * 4 + t];
            af[im][1] = sa[(r + 8) * 4 + t];
        }
#pragma unroll
        for (int in = 0; in < 8; ++in) {
            uint4 bq = sb[(wn * 64 + in * 8 + g) * 4 + t];
#pragma unroll
            for (int im = 0; im < 4; ++im) {
                mma_f16(acc[im][in], af[im][0].x, af[im][1].x, af[im][0].y, af[im][1].y, bq.x, bq.y);
                mma_f16(acc[im][in], af[im][0].z, af[im][1].z, af[im][0].w, af[im][1].w, bq.z, bq.w);
            }
        }
    }

#pragma unroll
    for (int im = 0; im < 4; ++im) {
        int r0g = m0 + wm * 64 + im * 16 + g;
#pragma unroll
        for (int in = 0; in < 8; ++in) {
            int c0 = n0 + wn * 64 + in * 8 + 2 * t;
            *(float2*)&C[(size_t)r0g * 2048 + c0] =
                make_float2(acc[im][in][0], acc[im][in][1]);
            *(float2*)&C[(size_t)(r0g + 8) * 2048 + c0] =
                make_float2(acc[im][in][2], acc[im][in][3]);
        }
    }
}

// ---------------- fused flash attention fp16 (Br=64, Bc=64, 4 warps, 2 CTA/SM) ----------------
#define FL_KOFF 12288
#define FL_VOFF 36864
#define FLASH_SMEM (53248 * 2)

__global__ __launch_bounds__(128, 2)
void flash_kernel() {
    extern __shared__ __half smh[];
    __half* Qs = smh;
    __half* Ks = smh + FL_KOFF;
    __half* Vs = smh + FL_VOFF;

    const int tid = threadIdx.x;
    const int m0 = blockIdx.x * 64;
    const int bh = blockIdx.y;
    const int b = bh >> 4, h = bh & 15;

    const __half* Qg = g_QfH + ((size_t)bh * M_ + m0) * DQK_;
    const __half* Kg = g_KfH + (size_t)bh * N_ * DQK_;
    const __half* Vg = g_VtH + (size_t)bh * DH_ * N_;

#pragma unroll
    for (int i = 0; i < 12; ++i) {
        int c = tid + i * 128;
        int row = c / 24, cc = c % 24;
        int phys = cc ^ ((row & 1) << 2);
        cp_async16h(Qs + row * 192 + phys * 8, Qg + (size_t)row * 192 + cc * 8);
    }
    cp_commit();

    auto load_K = [&](int j, int buf) {
        const __half* src = Kg + (size_t)j * 64 * DQK_;
        __half* dst = Ks + buf * 12288;
#pragma unroll
        for (int i = 0; i < 12; ++i) {
            int c = tid + i * 128;
            int row = c / 24, cc = c % 24;
            int phys = cc ^ ((row & 1) << 2);
            cp_async16h(dst + row * 192 + phys * 8, src + (size_t)row * 192 + cc * 8);
        }
        cp_commit();
    };
    auto load_V = [&](int j, int buf) {
        __half* dst = Vs + buf * 8192;
#pragma unroll
        for (int i = 0; i < 8; ++i) {
            int c = tid + i * 128;
            int row = c >> 3, cc = c & 7;
            int phys = cc ^ ((row & 1) << 2);
            cp_async16h(dst + row * 64 + phys * 8, Vg + (size_t)row * N_ + j * 64 + cc * 8);
        }
        cp_commit();
    };

    load_K(0, 0);
    load_V(0, 0);

    const int warp = tid >> 5, lane = tid & 31;
    const int g = lane >> 2, t = lane & 3;
    const int r0 = warp * 16 + g;
    const int swz = (g & 1) << 2;
    const int qr0 = r0 * 24, qr1 = (r0 + 8) * 24;

    float o[16][4] = {};
    float m0r = -1e30f, m1r = -1e30f, l0 = 0.f, l1 = 0.f;

    for (int j = 0; j < N_ / 64; ++j) {
        cp_wait<0>();
        __syncthreads();
        if (j + 1 < N_ / 64) { load_K(j + 1, (j + 1) & 1); load_V(j + 1, (j + 1) & 1); }

        const uint4* Ks4 = (const uint4*)(Ks + (j & 1) * 12288);
        const uint4* Vs4 = (const uint4*)(Vs + (j & 1) * 8192);
        const uint4* Qs4 = (const uint4*)Qs;

        // ---- S = Q K^T : warp tile 16x64 ----
        float s[8][4] = {};
#pragma unroll
        for (int blk = 0; blk < 6; ++blk) {
            int c = (blk * 4 + t) ^ swz;
            uint4 q0 = Qs4[qr0 + c];
            uint4 q1 = Qs4[qr1 + c];
#pragma unroll
            for (int nf = 0; nf < 8; ++nf) {
                uint4 kq = Ks4[(nf * 8 + g) * 24 + c];
                mma_f16(s[nf], q0.x, q1.x, q0.y, q1.y, kq.x, kq.y);
                mma_f16(s[nf], q0.z, q1.z, q0.w, q1.w, kq.z, kq.w);
            }
        }

        // ---- warp-local online softmax (Q pre-scaled) ----
        float mx0 = -1e30f, mx1 = -1e30f;
#pragma unroll
        for (int nf = 0; nf < 8; ++nf) {
            mx0 = fmaxf(mx0, fmaxf(s[nf][0], s[nf][1]));
            mx1 = fmaxf(mx1, fmaxf(s[nf][2], s[nf][3]));
        }
        mx0 = fmaxf(mx0, __shfl_xor_sync(0xffffffffu, mx0, 1));
        mx0 = fmaxf(mx0, __shfl_xor_sync(0xffffffffu, mx0, 2));
        mx1 = fmaxf(mx1, __shfl_xor_sync(0xffffffffu, mx1, 1));
        mx1 = fmaxf(mx1, __shfl_xor_sync(0xffffffffu, mx1, 2));
        float nm0 = fmaxf(m0r, mx0), nm1 = fmaxf(m1r, mx1);
        float sc0 = __expf(m0r - nm0), sc1 = __expf(m1r - nm1);
        m0r = nm0; m1r = nm1;

        float sum0 = 0.f, sum1 = 0.f;
        uint32_t plo[8], phi[8];
#pragma unroll
        for (int nf = 0; nf < 8; ++nf) {
            float p0 = __expf(s[nf][0] - m0r), p1 = __expf(s[nf][1] - m0r);
            float p2 = __expf(s[nf][2] - m1r), p3 = __expf(s[nf][3] - m1r);
            sum0 += p0 + p1; sum1 += p2 + p3;
            plo[nf] = h2u(__floats2half2_rn(p0, p1));
            phi[nf] = h2u(__floats2half2_rn(p2, p3));
        }
        sum0 += __shfl_xor_sync(0xffffffffu, sum0, 1);
        sum0 += __shfl_xor_sync(0xffffffffu, sum0, 2);
        sum1 += __shfl_xor_sync(0xffffffffu, sum1, 1);
        sum1 += __shfl_xor_sync(0xffffffffu, sum1, 2);
        l0 = l0 * sc0 + sum0;
        l1 = l1 * sc1 + sum1;
#pragma unroll
        for (int nf = 0; nf < 16; ++nf) {
            o[nf][0] *= sc0; o[nf][1] *= sc0; o[nf][2] *= sc1; o[nf][3] *= sc1;
        }

        // ---- O += P @ V ----
#pragma unroll
        for (int blk = 0; blk < 2; ++blk) {
            int c = (blk * 4 + t) ^ swz;
            uint32_t a00 = plo[4*blk],     a01 = phi[4*blk];
            uint32_t a02 = plo[4*blk + 1], a03 = phi[4*blk + 1];
            uint32_t a10 = plo[4*blk + 2], a11 = phi[4*blk + 2];
            uint32_t a12 = plo[4*blk + 3], a13 = phi[4*blk + 3];
#pragma unroll
            for (int nf = 0; nf < 16; ++nf) {
                uint4 vq = Vs4[(nf * 8 + g) * 8 + c];
                mma_f16(o[nf], a00, a01, a02, a03, vq.x, vq.y);
                mma_f16(o[nf], a10, a11, a12, a13, vq.z, vq.w);
            }
        }
    }

    float inv0 = 1.f / l0;
    float inv1 = 1.f / l1;
#pragma unroll
    for (int nf = 0; nf < 16; ++nf) {
        int cpos = h * 128 + (nf >> 2) * 32 + 8 * t + 2 * (nf & 3);
        size_t base0 = ((size_t)(b * M_) + m0 + r0) * 2048 + cpos;
        *(__half2*)&g_AoH[base0] = __floats2half2_rn(o[nf][0] * inv0, o[nf][1] * inv0);
        *(__half2*)&g_AoH[base0 + (size_t)8 * 2048] =
            __floats2half2_rn(o[nf][2] * inv1, o[nf][3] * inv1);
    }
}

// ---------------- launch ----------------
extern "C" void kernel_launch(void* const* d_in, const int* in_sizes, int n_in,
                              void* d_out, int out_size) {
    const float* query = (const float*)d_in[0];
    const float* keyv  = (const float*)d_in[1];
    const float* W_QC  = (const float*)d_in[2];
    const float* W_KC  = (const float*)d_in[3];
    const float* W_QR  = (const float*)d_in[4];
    const float* W_KR  = (const float*)d_in[5];
    const float* W_V   = (const float*)d_in[6];
    const float* W_O   = (const float*)d_in[7];
    float* out = (float*)d_out;

    static __half *pAo = nullptr, *pWo;
    if (!pAo) {
        cudaFuncSetAttribute(proj_all, cudaFuncAttributeMaxDynamicSharedMemorySize, GEMM_SMEM);
        cudaFuncSetAttribute(gemm_out, cudaFuncAttributeMaxDynamicSharedMemorySize, GEMM_SMEM);
        cudaFuncSetAttribute(flash_kernel, cudaFuncAttributeMaxDynamicSharedMemorySize, FLASH_SMEM);
        cudaGetSymbolAddress((void**)&pAo, g_AoH);
        cudaGetSymbolAddress((void**)&pWo, g_WoH);
    }

    rope_cache_kernel<<<256, 256>>>();

    conv_all<<<(NB_TOT + 255) / 256, 256>>>(
        (const float4*)query, (const float4*)keyv,
        (const float4*)W_QC, (const float4*)W_KC,
        (const float4*)W_V,  (const float4*)W_O,
        (const float4*)W_QR, (const float4*)W_KR);

    dim3 thr(128);
    proj_all<<<dim3(64, 32), thr, GEMM_SMEM>>>();
    transpose_v_kernel<<<dim3(4, 64, 32), dim3(32, 8)>>>();
    flash_kernel<<<dim3(32, 32), thr, FLASH_SMEM>>>();
    gemm_out<<<dim3(16, 32), thr, GEMM_SMEM>>>(pAo, pWo, out);
}